// round 1
// baseline (speedup 1.0000x reference)
#include <cuda_runtime.h>
#include <cstdint>

#define BB 8
#define HH 180
#define WW 180
#define NF 24
#define NB 31
#define NLUT 16384
#define SWID 192              // scratch row stride (W + pads)
#define TILE 30               // output tile (6x6 tiles exactly covers 180)
#define PIX (HH*WW)           // 32400 per image
#define NPIX (BB*PIX)         // 259200

typedef unsigned long long ull;

// ---------------- device scratch (static; no allocation) ----------------
__device__ float  d_scratch[BB*NF*HH*SWID];   // ~26.5 MB, zero-init at load
__device__ float2 d_lut[NLUT];                // (y_i, y_{i+1}-y_i)
__device__ float2 d_filt2[NF*26];             // (c,c) pairs, stride 26 (16B-aligned rows)
__device__ float2 d_kt2[NF*26];               // flipped kernels, duplicated pairs
__device__ float  d_Msum;

// ---------------- f32x2 helpers ----------------
__device__ __forceinline__ ull fma2(ull a, ull b, ull c) {
    ull d;
    asm("fma.rn.f32x2 %0, %1, %2, %3;" : "=l"(d) : "l"(a), "l"(b), "l"(c));
    return d;
}
__device__ __forceinline__ ull pack2(float lo, float hi) {
    ull r;
    asm("mov.b64 %0, {%1, %2};" : "=l"(r) : "f"(lo), "f"(hi));
    return r;
}
__device__ __forceinline__ void unpack2(ull v, float& lo, float& hi) {
    asm("mov.b64 {%0, %1}, %2;" : "=f"(lo), "=f"(hi) : "l"(v));
}

// ---------------- K0: prep (LUT, filter pairs, pad zero, Msum=0) ----------------
__global__ void k_prep(const float* __restrict__ filters,
                       const float* __restrict__ mu,
                       const float* __restrict__ weights) {
    const int tid = blockIdx.x * blockDim.x + threadIdx.x;
    const int stride = gridDim.x * blockDim.x;
    const float h = 4.0f / (float)NLUT;   // exact 2^-12

    if (tid == 0) d_Msum = 0.0f;

    // LUT: phi(x) = sum_j w_j exp(-50*(x-mu_j)^2) over x in [-2,2]
    for (int i = tid; i < NLUT; i += stride) {
        float x0 = fmaf((float)i, h, -2.0f);
        float x1 = fmaf((float)(i + 1), h, -2.0f);
        float y0 = 0.0f, y1 = 0.0f;
        #pragma unroll 1
        for (int j = 0; j < NB; j++) {
            float m = __ldg(&mu[j]);
            float w = __ldg(&weights[j]);
            float t0 = x0 - m, t1 = x1 - m;
            y0 += w * __expf(-50.0f * t0 * t0);
            y1 += w * __expf(-50.0f * t1 * t1);
        }
        d_lut[i] = make_float2(y0, y1 - y0);
    }

    // duplicated-pair filter tables
    for (int i = tid; i < NF * 25; i += stride) {
        int f = i / 25, t = i % 25;
        int a = t / 5, b = t % 5;
        float c = __ldg(&filters[i]);
        d_filt2[f * 26 + t] = make_float2(c, c);
        float ck = __ldg(&filters[f * 25 + (4 - a) * 5 + (4 - b)]);
        d_kt2[f * 26 + t] = make_float2(ck, ck);
    }

    // zero scratch pad columns (idx 0,1 and 184..191) for every row
    const int NROWS = BB * NF * HH;
    for (int i = tid; i < NROWS * 10; i += stride) {
        int row = i / 10, c = i % 10;
        int col = (c < 2) ? c : (182 + c);   // 0,1,184..191
        d_scratch[row * SWID + col] = 0.0f;
    }
}

// ---------------- K1: weighted reduction for M ----------------
// sum_p boxsum(p) = sum_q u(q)*ny(q)*nx(q);  M = S/(9*NPIX) + 0.001
__global__ void k_reduce(const float* __restrict__ u) {
    float s = 0.0f;
    for (int i = blockIdx.x * blockDim.x + threadIdx.x; i < NPIX;
         i += gridDim.x * blockDim.x) {
        int p = i % PIX;
        int y = p / WW, x = p % WW;
        float wy = (y == 0 || y == HH - 1) ? 2.0f : 3.0f;
        float wx = (x == 0 || x == WW - 1) ? 2.0f : 3.0f;
        s += u[i] * wy * wx;
    }
    #pragma unroll
    for (int o = 16; o > 0; o >>= 1) s += __shfl_xor_sync(0xFFFFFFFFu, s, o);
    __shared__ float ws[8];
    int wid = threadIdx.x >> 5, lane = threadIdx.x & 31;
    if (lane == 0) ws[wid] = s;
    __syncthreads();
    if (threadIdx.x == 0) {
        float bs = 0.0f;
        #pragma unroll
        for (int w = 0; w < 8; w++) bs += ws[w];
        atomicAdd(&d_Msum, bs);
    }
}

// ---------------- K2: conv1 + RBF(LUT) + boxsum scale -> scratch ----------------
__global__ __launch_bounds__(256, 2) void k_stage2(const float* __restrict__ u) {
    __shared__ __align__(16) float su[34 * 36];
    __shared__ __align__(16) float2 sf[NF * 26];

    const int tid = threadIdx.x;
    const int b = blockIdx.z;
    const int gx0 = blockIdx.x * TILE;
    const int gy0 = blockIdx.y * TILE;

    for (int i = tid; i < NF * 26; i += 256) sf[i] = d_filt2[i];

    // load u tile rows [gy0-2, gy0+31], cols [gx0-2, gx0+33], zero-padded
    const float* ub = u + b * PIX;
    for (int i = tid; i < 34 * 36; i += 256) {
        int r = i / 36, c = i % 36;
        int gy = gy0 - 2 + r, gx = gx0 - 2 + c;
        float v = 0.0f;
        if (gy >= 0 && gy < HH && gx >= 0 && gx < WW) v = __ldg(&ub[gy * WW + gx]);
        su[i] = v;
    }
    __syncthreads();

    if (tid < 240) {
        const int oy = tid >> 3;
        const int ox = (tid & 7) << 2;

        float pv[5][8];
        #pragma unroll
        for (int r = 0; r < 5; r++) {
            float4 a = *(const float4*)&su[(oy + r) * 36 + ox];
            float4 bq = *(const float4*)&su[(oy + r) * 36 + ox + 4];
            pv[r][0] = a.x;  pv[r][1] = a.y;  pv[r][2] = a.z;  pv[r][3] = a.w;
            pv[r][4] = bq.x; pv[r][5] = bq.y; pv[r][6] = bq.z; pv[r][7] = bq.w;
        }

        // boxsum (9*u_sigma) for 4 pixels + mask x>=180 to zero
        float cs[6];
        #pragma unroll
        for (int j = 0; j < 6; j++) cs[j] = pv[1][j + 1] + pv[2][j + 1] + pv[3][j + 1];
        float usig[4];
        #pragma unroll
        for (int i = 0; i < 4; i++) usig[i] = cs[i] + cs[i + 1] + cs[i + 2];
        const int gxo = gx0 + ox;
        #pragma unroll
        for (int i = 0; i < 4; i++) if (gxo + i >= WW) usig[i] = 0.0f;

        // pair-pack patch rows
        ull P[5][7];
        #pragma unroll
        for (int r = 0; r < 5; r++)
            #pragma unroll
            for (int j = 0; j < 7; j++) P[r][j] = pack2(pv[r][j], pv[r][j + 1]);

        const int gy = gy0 + oy;
        float* dst0 = &d_scratch[((size_t)(b * NF) * HH + gy) * SWID + gxo + 2];

        #pragma unroll 1
        for (int f = 0; f < NF; f++) {
            const float2* cf = &sf[f * 26];
            ull A = 0ULL, Bq = 0ULL;
            #pragma unroll
            for (int r = 0; r < 5; r++) {
                #pragma unroll
                for (int dx = 0; dx < 5; dx++) {
                    ull c = *(const ull*)&cf[r * 5 + dx];
                    A  = fma2(c, P[r][dx], A);
                    Bq = fma2(c, P[r][dx + 2], Bq);
                }
            }
            float cv[4];
            unpack2(A, cv[0], cv[1]);
            unpack2(Bq, cv[2], cv[3]);

            float sv[4];
            #pragma unroll
            for (int i = 0; i < 4; i++) {
                float t = fmaf(cv[i], 4096.0f, 8192.0f);   // (x+2)/h
                t = fminf(fmaxf(t, 0.0f), 16383.5f);
                int ii = (int)t;
                float fr = t - (float)ii;
                float2 L = __ldg(&d_lut[ii]);
                sv[i] = usig[i] * fmaf(fr, L.y, L.x);
            }
            float* dst = dst0 + (size_t)f * (HH * SWID);
            *(float2*)(dst)     = make_float2(sv[0], sv[1]);
            *(float2*)(dst + 2) = make_float2(sv[2], sv[3]);
        }
    }
}

// ---------------- K3: conv2 (24->1, flipped) + reaction + clip ----------------
__global__ __launch_bounds__(256, 2) void k_stage3(const float* __restrict__ u,
                                                   const float* __restrict__ fin,
                                                   const float* __restrict__ lam,
                                                   float* __restrict__ out) {
    __shared__ __align__(16) float2 sk[NF * 26];
    const int tid = threadIdx.x;
    const int b = blockIdx.z;
    const int gx0 = blockIdx.x * TILE;
    const int gy0 = blockIdx.y * TILE;

    for (int i = tid; i < NF * 26; i += 256) sk[i] = d_kt2[i];
    __syncthreads();

    const float M = d_Msum * (1.0f / (9.0f * (float)NPIX)) + 0.001f;
    const float sc = 1.0f / (9.0f * M);

    if (tid < 240) {
        const int oy = tid >> 3;
        const int ox = (tid & 7) << 2;
        const int gy = gy0 + oy;
        const int gx = gx0 + ox;

        bool rv[5];
        #pragma unroll
        for (int r = 0; r < 5; r++) {
            int ty = gy - 2 + r;
            rv[r] = (ty >= 0 && ty < HH);
        }

        ull A = 0ULL, Bq = 0ULL;
        #pragma unroll 1
        for (int f = 0; f < NF; f++) {
            const float2* cf = &sk[f * 26];
            const float* plane = &d_scratch[(size_t)(b * NF + f) * HH * SWID];
            #pragma unroll
            for (int r = 0; r < 5; r++) {
                float2 e0 = make_float2(0.f, 0.f), e1 = e0, e2 = e0, e3 = e0;
                if (rv[r]) {
                    const float* rp = plane + (gy - 2 + r) * SWID + gx;  // idx of pair j=gx-2
                    e0 = *(const float2*)(rp);
                    e1 = *(const float2*)(rp + 2);
                    e2 = *(const float2*)(rp + 4);
                    e3 = *(const float2*)(rp + 6);
                }
                ull E0 = pack2(e0.x, e0.y), E1 = pack2(e1.x, e1.y);
                ull E2 = pack2(e2.x, e2.y), E3 = pack2(e3.x, e3.y);
                ull o0 = pack2(e0.y, e1.x);
                ull o1 = pack2(e1.y, e2.x);
                ull o2 = pack2(e2.y, e3.x);
                ull c0 = *(const ull*)&cf[r * 5 + 0];
                ull c1 = *(const ull*)&cf[r * 5 + 1];
                ull c2 = *(const ull*)&cf[r * 5 + 2];
                ull c3 = *(const ull*)&cf[r * 5 + 3];
                ull c4 = *(const ull*)&cf[r * 5 + 4];
                A = fma2(c0, E0, A);  Bq = fma2(c0, E1, Bq);
                A = fma2(c1, o0, A);  Bq = fma2(c1, o1, Bq);
                A = fma2(c2, E1, A);  Bq = fma2(c2, E2, Bq);
                A = fma2(c3, o1, A);  Bq = fma2(c3, o2, Bq);
                A = fma2(c4, E2, A);  Bq = fma2(c4, E3, Bq);
            }
        }
        float dif[4];
        unpack2(A, dif[0], dif[1]);
        unpack2(Bq, dif[2], dif[3]);

        const float lamv = __ldg(lam);
        #pragma unroll
        for (int i = 0; i < 4; i++) {
            int x = gx + i;
            if (x < WW) {
                int idx = b * PIX + gy * WW + x;
                float uu = __ldg(&u[idx]);
                float fv = __ldg(&fin[idx]);
                float re = lamv * (uu - fv) / (uu * uu + 1e-3f);
                float val = uu - dif[i] * sc - re;
                out[idx] = fminf(fmaxf(val, 0.0f), 1.0f);
            }
        }
    }
}

// ---------------- launch ----------------
extern "C" void kernel_launch(void* const* d_in, const int* in_sizes, int n_in,
                              void* d_out, int out_size) {
    const float* u       = (const float*)d_in[0];
    const float* f       = (const float*)d_in[1];
    const float* filters = (const float*)d_in[2];
    const float* lam     = (const float*)d_in[3];
    const float* mu      = (const float*)d_in[4];
    const float* weights = (const float*)d_in[5];
    float* out = (float*)d_out;

    k_prep<<<128, 256>>>(filters, mu, weights);
    k_reduce<<<160, 256>>>(u);

    dim3 grid(WW / TILE, HH / TILE, BB);   // 6 x 6 x 8
    k_stage2<<<grid, 256>>>(u);
    k_stage3<<<grid, 256>>>(u, f, lam, out);
}

// round 2
// speedup vs baseline: 1.0446x; 1.0446x over previous
#include <cuda_runtime.h>
#include <cstdint>

#define BB 8
#define HH 180
#define WW 180
#define NF 24
#define NB 31
#define NLUT 16384
#define PIX (HH*WW)
#define NPIX (BB*PIX)

typedef unsigned long long ull;

// ---------------- device globals (no allocation) ----------------
__device__ float2 d_lut[NLUT];      // (y_i, y_{i+1}-y_i)
__device__ float2 d_fA[NF*30];      // conv1 coeffs as (c,c) pairs, 5 rows x 6 (48B rows)
__device__ float2 d_fB[NF*30];      // flipped coeffs for conv2, same layout
__device__ float  d_Msum;

// ---------------- f32x2 helpers ----------------
__device__ __forceinline__ ull fma2(ull a, ull b, ull c) {
    ull d;
    asm("fma.rn.f32x2 %0, %1, %2, %3;" : "=l"(d) : "l"(a), "l"(b), "l"(c));
    return d;
}
__device__ __forceinline__ ull pack2(float lo, float hi) {
    ull r;
    asm("mov.b64 %0, {%1, %2};" : "=l"(r) : "f"(lo), "f"(hi));
    return r;
}
__device__ __forceinline__ void unpack2(ull v, float& lo, float& hi) {
    asm("mov.b64 {%0, %1}, %2;" : "=f"(lo), "=f"(hi) : "l"(v));
}

__device__ __forceinline__ float lutphi(float x) {
    float t = fmaf(x, 4096.0f, 8192.0f);        // (x+2)/2^-12
    t = fminf(fmaxf(t, 0.0f), 16383.5f);
    int ii = (int)t;
    float fr = t - (float)ii;
    float2 L = __ldg(&d_lut[ii]);
    return fmaf(fr, L.y, L.x);
}

// ---------------- K0: prep (LUT + filter tables) ----------------
__global__ void k_prep(const float* __restrict__ filters,
                       const float* __restrict__ mu,
                       const float* __restrict__ weights) {
    const int tid = blockIdx.x * blockDim.x + threadIdx.x;
    const int stride = gridDim.x * blockDim.x;
    const float h = 4.0f / (float)NLUT;

    if (tid == 0) d_Msum = 0.0f;

    for (int i = tid; i < NLUT; i += stride) {
        float x0 = fmaf((float)i, h, -2.0f);
        float x1 = fmaf((float)(i + 1), h, -2.0f);
        float y0 = 0.0f, y1 = 0.0f;
        #pragma unroll 1
        for (int j = 0; j < NB; j++) {
            float m = __ldg(&mu[j]);
            float w = __ldg(&weights[j]);
            float t0 = x0 - m, t1 = x1 - m;
            y0 += w * __expf(-50.0f * t0 * t0);
            y1 += w * __expf(-50.0f * t1 * t1);
        }
        d_lut[i] = make_float2(y0, y1 - y0);
    }

    for (int i = tid; i < NF * 30; i += stride) {
        int f = i / 30, t = i % 30;
        int r = t / 6, c = t % 6;
        float wA = 0.0f, wB = 0.0f;
        if (c < 5) {
            wA = __ldg(&filters[f * 25 + r * 5 + c]);
            wB = __ldg(&filters[f * 25 + (4 - r) * 5 + (4 - c)]);
        }
        d_fA[i] = make_float2(wA, wA);
        d_fB[i] = make_float2(wB, wB);
    }
}

// ---------------- K1: weighted reduction for M ----------------
__global__ void k_reduce(const float* __restrict__ u) {
    float s = 0.0f;
    for (int i = blockIdx.x * blockDim.x + threadIdx.x; i < NPIX;
         i += gridDim.x * blockDim.x) {
        int p = i % PIX;
        int y = p / WW, x = p % WW;
        float wy = (y == 0 || y == HH - 1) ? 2.0f : 3.0f;
        float wx = (x == 0 || x == WW - 1) ? 2.0f : 3.0f;
        s += u[i] * wy * wx;
    }
    #pragma unroll
    for (int o = 16; o > 0; o >>= 1) s += __shfl_xor_sync(0xFFFFFFFFu, s, o);
    __shared__ float ws[8];
    int wid = threadIdx.x >> 5, lane = threadIdx.x & 31;
    if (lane == 0) ws[wid] = s;
    __syncthreads();
    if (threadIdx.x == 0) {
        float bs = 0.0f;
        #pragma unroll
        for (int w = 0; w < 8; w++) bs += ws[w];
        atomicAdd(&d_Msum, bs);
    }
}

// 5-tap dual-pair conv macro (pairs: A=(q0,q0+1), B=(q0+2,q0+3))
#define CONV5(a0, a1, C, E0, O0, E1, O1, E2, O2, E3)                         \
    do {                                                                     \
        a0 = fma2((C)[0], E0, a0); a0 = fma2((C)[1], O0, a0);                \
        a0 = fma2((C)[2], E1, a0); a0 = fma2((C)[3], O1, a0);                \
        a0 = fma2((C)[4], E2, a0);                                           \
        a1 = fma2((C)[0], E1, a1); a1 = fma2((C)[1], O1, a1);                \
        a1 = fma2((C)[2], E2, a1); a1 = fma2((C)[3], O2, a1);                \
        a1 = fma2((C)[4], E3, a1);                                           \
    } while (0)

// ---------------- fused kernel: conv1 + RBF + scale + conv2 + reaction ----------------
__global__ __launch_bounds__(128) void k_fused(const float* __restrict__ u,
                                               const float* __restrict__ fin,
                                               const float* __restrict__ lam,
                                               float* __restrict__ out) {
    __shared__ __align__(16) float su[40 * 40];
    __shared__ __align__(16) float buf0[36 * 40];
    __shared__ __align__(16) float buf1[36 * 40];
    __shared__ __align__(16) float2 sfa[NF * 30];
    __shared__ __align__(16) float2 sfb[NF * 30];

    const int tid = threadIdx.x;
    const int b = blockIdx.z;
    const int gx0 = blockIdx.x * 30;
    const int gy0 = blockIdx.y * 30;

    for (int i = tid; i < NF * 30; i += 128) { sfa[i] = d_fA[i]; sfb[i] = d_fB[i]; }

    // u tile: su[r][c] = u[gy0-4+r][gx0-4+c], zero padded; rows 38,39 padding
    const float* ub = u + b * PIX;
    for (int i = tid; i < 1600; i += 128) {
        int r = i / 40, c = i % 40;
        int gy = gy0 - 4 + r, gx = gx0 - 4 + c;
        float v = 0.0f;
        if (gy >= 0 && gy < HH && gx >= 0 && gx < WW) v = __ldg(&ub[gy * WW + gx]);
        su[i] = v;
    }
    __syncthreads();

    // A-phase task (tid<108): 3 phi rows x 4 cols
    const int p0 = (tid / 9) * 3;          // 0..33
    const int q0 = (tid % 9) * 4;          // 0..32
    // B-phase task (tid<80): 3 out rows x 4 cols
    const int oy0 = (tid / 8) * 3;         // 0..27
    const int ox0 = (tid % 8) * 4;         // 0..28

    // A masks: phi position (p,q) -> global (gy0-2+p, gx0-2+q)
    float rowm[3], colm[4];
    #pragma unroll
    for (int i = 0; i < 3; i++) {
        int gy = gy0 - 2 + p0 + i;
        rowm[i] = (gy >= 0 && gy < HH) ? 1.0f : 0.0f;
    }
    #pragma unroll
    for (int j = 0; j < 4; j++) {
        int gx = gx0 - 2 + q0 + j;
        colm[j] = (gx >= 0 && gx < WW) ? 1.0f : 0.0f;
    }

    // persistent conv2 accumulators
    ull dA[3], dB[3];
    #pragma unroll
    for (int i = 0; i < 3; i++) { dA[i] = 0ULL; dB[i] = 0ULL; }

    #pragma unroll 1
    for (int f = 0; f < NF; f++) {
        float* bw = (f & 1) ? buf1 : buf0;

        // ---------- stage A: conv1 + LUT + boxsum into bw ----------
        if (tid < 108) {
            const float2* cfA = &sfa[f * 30];
            ull A0 = 0, B0 = 0, A1 = 0, B1 = 0, A2 = 0, B2 = 0;
            float u0[4] = {0, 0, 0, 0}, u1[4] = {0, 0, 0, 0}, u2[4] = {0, 0, 0, 0};
            ull cc[5], cp[5], cq[5];
            #pragma unroll
            for (int k = 0; k < 7; k++) {
                const ulonglong2* rp = (const ulonglong2*)(su + (p0 + k) * 40 + q0);
                ulonglong2 ra = rp[0], rb = rp[1];
                ull E0 = ra.x, E1 = ra.y, E2 = rb.x, E3 = rb.y;
                float v0, v1, v2, v3, v4, v5, v6, v7;
                unpack2(E0, v0, v1); unpack2(E1, v2, v3);
                unpack2(E2, v4, v5); unpack2(E3, v6, v7);
                ull O0 = pack2(v1, v2), O1 = pack2(v3, v4), O2 = pack2(v5, v6);

                // boxsum horizontal 3-sums
                if (k >= 1 && k <= 5) {
                    float a_ = v2 + v3, b_ = v4 + v5;
                    float hs0 = v1 + a_, hs1 = a_ + v4, hs2 = v3 + b_, hs3 = b_ + v6;
                    if (k >= 1 && k <= 3) { u0[0] += hs0; u0[1] += hs1; u0[2] += hs2; u0[3] += hs3; }
                    if (k >= 2 && k <= 4) { u1[0] += hs0; u1[1] += hs1; u1[2] += hs2; u1[3] += hs3; }
                    if (k >= 3 && k <= 5) { u2[0] += hs0; u2[1] += hs1; u2[2] += hs2; u2[3] += hs3; }
                }

                if (k <= 4) {
                    const ulonglong2* cv = (const ulonglong2*)(cfA + k * 6);
                    ulonglong2 x0 = cv[0], x1 = cv[1];
                    cc[0] = x0.x; cc[1] = x0.y; cc[2] = x1.x; cc[3] = x1.y;
                    cc[4] = *(const ull*)(cfA + k * 6 + 4);
                    CONV5(A0, B0, cc, E0, O0, E1, O1, E2, O2, E3);
                }
                if (k >= 1 && k <= 5) CONV5(A1, B1, cp, E0, O0, E1, O1, E2, O2, E3);
                if (k >= 2)           CONV5(A2, B2, cq, E0, O0, E1, O1, E2, O2, E3);
                #pragma unroll
                for (int t = 0; t < 5; t++) { cq[t] = cp[t]; cp[t] = cc[t]; }
            }

            // LUT + scale + store rows
            #pragma unroll
            for (int i = 0; i < 3; i++) {
                float c0, c1, c2, c3;
                if (i == 0) { unpack2(A0, c0, c1); unpack2(B0, c2, c3); }
                else if (i == 1) { unpack2(A1, c0, c1); unpack2(B1, c2, c3); }
                else { unpack2(A2, c0, c1); unpack2(B2, c2, c3); }
                const float* uu = (i == 0) ? u0 : (i == 1) ? u1 : u2;
                float4 res;
                res.x = lutphi(c0) * (uu[0] * rowm[i] * colm[0]);
                res.y = lutphi(c1) * (uu[1] * rowm[i] * colm[1]);
                res.z = lutphi(c2) * (uu[2] * rowm[i] * colm[2]);
                res.w = lutphi(c3) * (uu[3] * rowm[i] * colm[3]);
                *(float4*)(bw + (p0 + i) * 40 + q0) = res;
            }
        }
        __syncthreads();

        // ---------- stage B: conv2 accumulate from bw ----------
        if (tid < 80) {
            const float2* cfB = &sfb[f * 30];
            ull cc[5], cp[5], cq[5];
            #pragma unroll
            for (int k = 0; k < 7; k++) {
                const ulonglong2* rp = (const ulonglong2*)(bw + (oy0 + k) * 40 + ox0);
                ulonglong2 ra = rp[0], rb = rp[1];
                ull E0 = ra.x, E1 = ra.y, E2 = rb.x, E3 = rb.y;
                float v0, v1, v2, v3, v4, v5, v6, v7;
                unpack2(E0, v0, v1); unpack2(E1, v2, v3);
                unpack2(E2, v4, v5); unpack2(E3, v6, v7);
                ull O0 = pack2(v1, v2), O1 = pack2(v3, v4), O2 = pack2(v5, v6);

                if (k <= 4) {
                    const ulonglong2* cv = (const ulonglong2*)(cfB + k * 6);
                    ulonglong2 x0 = cv[0], x1 = cv[1];
                    cc[0] = x0.x; cc[1] = x0.y; cc[2] = x1.x; cc[3] = x1.y;
                    cc[4] = *(const ull*)(cfB + k * 6 + 4);
                    CONV5(dA[0], dB[0], cc, E0, O0, E1, O1, E2, O2, E3);
                }
                if (k >= 1 && k <= 5) CONV5(dA[1], dB[1], cp, E0, O0, E1, O1, E2, O2, E3);
                if (k >= 2)           CONV5(dA[2], dB[2], cq, E0, O0, E1, O1, E2, O2, E3);
                #pragma unroll
                for (int t = 0; t < 5; t++) { cq[t] = cp[t]; cp[t] = cc[t]; }
            }
        }
    }

    // ---------- epilogue ----------
    if (tid < 80) {
        const float M = d_Msum * (1.0f / (9.0f * (float)NPIX)) + 0.001f;
        const float sc = 1.0f / (9.0f * M);
        const float lamv = __ldg(lam);
        #pragma unroll
        for (int i = 0; i < 3; i++) {
            float dv[4];
            unpack2(dA[i], dv[0], dv[1]);
            unpack2(dB[i], dv[2], dv[3]);
            const int gy = gy0 + oy0 + i;
            #pragma unroll
            for (int j = 0; j < 4; j++) {
                int ox = ox0 + j;
                if (ox < 30) {
                    int gx = gx0 + ox;
                    int idx = b * PIX + gy * WW + gx;
                    float uu = su[(oy0 + i + 4) * 40 + (ox + 4)];
                    float fv = __ldg(&fin[idx]);
                    float re = lamv * (uu - fv) / (uu * uu + 1e-3f);
                    float val = uu - dv[j] * sc - re;
                    out[idx] = fminf(fmaxf(val, 0.0f), 1.0f);
                }
            }
        }
    }
}

// ---------------- launch ----------------
extern "C" void kernel_launch(void* const* d_in, const int* in_sizes, int n_in,
                              void* d_out, int out_size) {
    const float* u       = (const float*)d_in[0];
    const float* f       = (const float*)d_in[1];
    const float* filters = (const float*)d_in[2];
    const float* lam     = (const float*)d_in[3];
    const float* mu      = (const float*)d_in[4];
    const float* weights = (const float*)d_in[5];
    float* out = (float*)d_out;

    k_prep<<<64, 256>>>(filters, mu, weights);
    k_reduce<<<148, 256>>>(u);

    dim3 grid(WW / 30, HH / 30, BB);   // 6 x 6 x 8 = 288 blocks
    k_fused<<<grid, 128>>>(u, f, lam, out);
}

// round 3
// speedup vs baseline: 1.1731x; 1.1230x over previous
#include <cuda_runtime.h>
#include <cstdint>

#define BB 8
#define HH 180
#define WW 180
#define NF 24
#define NB 31
#define NLUT 16384
#define PIX (HH*WW)
#define NPIX (BB*PIX)
#define PW 184                 // padded partial-plane stride

typedef unsigned long long ull;

// ---------------- device globals (no allocation) ----------------
__device__ float2 d_lut[NLUT];       // (y_i, y_{i+1}-y_i)
__device__ float2 d_fA[NF*30];       // conv1 coeffs as (c,c) pairs, 5 rows x 6
__device__ float2 d_fB[NF*30];       // flipped coeffs for conv2
__device__ float  d_bsums[96];       // per-block partial sums for M
__device__ float  d_part[2][BB*HH*PW];  // split-filter partial diffusion

// ---------------- f32x2 helpers ----------------
__device__ __forceinline__ ull fma2(ull a, ull b, ull c) {
    ull d;
    asm("fma.rn.f32x2 %0, %1, %2, %3;" : "=l"(d) : "l"(a), "l"(b), "l"(c));
    return d;
}
__device__ __forceinline__ ull pack2(float lo, float hi) {
    ull r;
    asm("mov.b64 %0, {%1, %2};" : "=l"(r) : "f"(lo), "f"(hi));
    return r;
}
__device__ __forceinline__ void unpack2(ull v, float& lo, float& hi) {
    asm("mov.b64 {%0, %1}, %2;" : "=f"(lo), "=f"(hi) : "l"(v));
}

__device__ __forceinline__ float lutphi(float x) {
    float t = fmaf(x, 4096.0f, 8192.0f);
    t = fminf(fmaxf(t, 0.0f), 16383.5f);
    int ii = (int)t;
    float fr = t - (float)ii;
    float2 L = __ldg(&d_lut[ii]);
    return fmaf(fr, L.y, L.x);
}

// ---------------- K0: merged prep (LUT+tables) and M-reduction ----------------
__global__ void k_pre(const float* __restrict__ filters,
                      const float* __restrict__ mu,
                      const float* __restrict__ weights,
                      const float* __restrict__ u) {
    const int blk = blockIdx.x, tid = threadIdx.x;
    if (blk < 64) {
        // LUT: one entry per thread, fully unrolled -> MUFU throughput bound
        const int i = blk * 256 + tid;
        const float h = 4.0f / (float)NLUT;
        float x0 = fmaf((float)i, h, -2.0f);
        float x1 = x0 + h;
        float y0 = 0.0f, y1 = 0.0f;
        #pragma unroll
        for (int j = 0; j < NB; j++) {
            float m = __ldg(&mu[j]);
            float w = __ldg(&weights[j]);
            float t0 = x0 - m, t1 = x1 - m;
            y0 += w * __expf(-50.0f * t0 * t0);
            y1 += w * __expf(-50.0f * t1 * t1);
        }
        d_lut[i] = make_float2(y0, y1 - y0);

        // filter tables on first 3 blocks
        if (blk < 3) {
            int t = blk * 256 + tid;
            if (t < NF * 30) {
                int f = t / 30, e = t % 30;
                int r = e / 6, c = e % 6;
                float wA = 0.0f, wB = 0.0f;
                if (c < 5) {
                    wA = __ldg(&filters[f * 25 + r * 5 + c]);
                    wB = __ldg(&filters[f * 25 + (4 - r) * 5 + (4 - c)]);
                }
                d_fA[t] = make_float2(wA, wA);
                d_fB[t] = make_float2(wB, wB);
            }
        }
    } else {
        // weighted sum of u (for M): S = sum u * ny * nx; float4 strides
        const int NG = BB * HH * 45;
        float s = 0.0f;
        for (int g = (blk - 64) * 256 + tid; g < NG; g += 96 * 256) {
            int b = g / (HH * 45);
            int r = g - b * (HH * 45);
            int gy = r / 45;
            int gx = (r - gy * 45) * 4;
            const float4 uu = *(const float4*)(u + b * PIX + gy * WW + gx);
            float wy = (gy == 0 || gy == HH - 1) ? 2.0f : 3.0f;
            float w0 = (gx == 0) ? 2.0f : 3.0f;
            float w3 = (gx + 3 == WW - 1) ? 2.0f : 3.0f;
            s += wy * (w0 * uu.x + 3.0f * uu.y + 3.0f * uu.z + w3 * uu.w);
        }
        #pragma unroll
        for (int o = 16; o > 0; o >>= 1) s += __shfl_xor_sync(0xFFFFFFFFu, s, o);
        __shared__ float ws[8];
        int wid = tid >> 5, lane = tid & 31;
        if (lane == 0) ws[wid] = s;
        __syncthreads();
        if (tid == 0) {
            float bs = 0.0f;
            #pragma unroll
            for (int w = 0; w < 8; w++) bs += ws[w];
            d_bsums[blk - 64] = bs;
        }
    }
}

// 5-tap dual-pair conv macro
#define CONV5(a0, a1, C, E0, O0, E1, O1, E2, O2, E3)                         \
    do {                                                                     \
        a0 = fma2((C)[0], E0, a0); a0 = fma2((C)[1], O0, a0);                \
        a0 = fma2((C)[2], E1, a0); a0 = fma2((C)[3], O1, a0);                \
        a0 = fma2((C)[4], E2, a0);                                           \
        a1 = fma2((C)[0], E1, a1); a1 = fma2((C)[1], O1, a1);                \
        a1 = fma2((C)[2], E2, a1); a1 = fma2((C)[3], O2, a1);                \
        a1 = fma2((C)[4], E3, a1);                                           \
    } while (0)

#define LOADROW(base)                                                        \
    const ulonglong2* rp_ = (const ulonglong2*)(base);                       \
    ulonglong2 ra_ = rp_[0], rb_ = rp_[1];                                   \
    ull E0 = ra_.x, E1 = ra_.y, E2 = rb_.x, E3 = rb_.y;                      \
    float v0, v1, v2, v3, v4, v5, v6, v7;                                    \
    unpack2(E0, v0, v1); unpack2(E1, v2, v3);                                \
    unpack2(E2, v4, v5); unpack2(E3, v6, v7);                                \
    ull O0 = pack2(v1, v2), O1 = pack2(v3, v4), O2 = pack2(v5, v6);          \
    (void)v0; (void)v7;

#define LOADCOEF(cf, k, cc)                                                  \
    do {                                                                     \
        const ulonglong2* cv_ = (const ulonglong2*)((cf) + (k) * 6);         \
        ulonglong2 x0_ = cv_[0], x1_ = cv_[1];                               \
        cc[0] = x0_.x; cc[1] = x0_.y; cc[2] = x1_.x; cc[3] = x1_.y;          \
        cc[4] = *(const ull*)((cf) + (k) * 6 + 4);                           \
    } while (0)

// ---------------- fused kernel: half the filters per block ----------------
__global__ __launch_bounds__(128, 4) void k_fused(const float* __restrict__ u) {
    __shared__ __align__(16) float su[40 * 40];
    __shared__ __align__(16) float buf0[36 * 40];
    __shared__ __align__(16) float buf1[36 * 40];
    __shared__ __align__(16) float2 sfa[12 * 30];
    __shared__ __align__(16) float2 sfb[12 * 30];

    const int tid = threadIdx.x;
    const int half = blockIdx.z & 1;
    const int b = blockIdx.z >> 1;
    const int f0 = half * 12;
    const int gx0 = blockIdx.x * 30;
    const int gy0 = blockIdx.y * 30;

    for (int i = tid; i < 360; i += 128) {
        sfa[i] = d_fA[f0 * 30 + i];
        sfb[i] = d_fB[f0 * 30 + i];
    }

    const float* ub = u + b * PIX;
    for (int i = tid; i < 1600; i += 128) {
        int r = i / 40, c = i % 40;
        int gy = gy0 - 4 + r, gx = gx0 - 4 + c;
        float v = 0.0f;
        if (gy >= 0 && gy < HH && gx >= 0 && gx < WW) v = __ldg(&ub[gy * WW + gx]);
        su[i] = v;
    }
    __syncthreads();

    // A task: 3 phi rows x 4 cols (tid<108); B task: 2 out rows x 4 cols (tid<120)
    const int p0 = (tid / 9) * 3;
    const int q0 = (tid % 9) * 4;
    const int oy0 = (tid >> 3) * 2;
    const int ox0 = (tid & 7) * 4;

    // hoisted boxsum with masks folded in
    float us0[4] = {0, 0, 0, 0}, us1[4] = {0, 0, 0, 0}, us2[4] = {0, 0, 0, 0};
    if (tid < 108) {
        #pragma unroll
        for (int k = 1; k <= 5; k++) {
            const float4* rp = (const float4*)(su + (p0 + k) * 40 + q0);
            float4 a = rp[0], bq = rp[1];
            float a_ = a.z + a.w, b_ = bq.x + bq.y;
            float hs0 = a.y + a_, hs1 = a_ + bq.x, hs2 = a.w + b_, hs3 = b_ + bq.z;
            if (k <= 3)           { us0[0] += hs0; us0[1] += hs1; us0[2] += hs2; us0[3] += hs3; }
            if (k >= 2 && k <= 4) { us1[0] += hs0; us1[1] += hs1; us1[2] += hs2; us1[3] += hs3; }
            if (k >= 3)           { us2[0] += hs0; us2[1] += hs1; us2[2] += hs2; us2[3] += hs3; }
        }
        #pragma unroll
        for (int j = 0; j < 4; j++) {
            int gx = gx0 - 2 + q0 + j;
            float cm = (gx >= 0 && gx < WW) ? 1.0f : 0.0f;
            int g0 = gy0 - 2 + p0;
            us0[j] *= cm * ((g0 >= 0 && g0 < HH) ? 1.0f : 0.0f);
            us1[j] *= cm * ((g0 + 1 >= 0 && g0 + 1 < HH) ? 1.0f : 0.0f);
            us2[j] *= cm * ((g0 + 2 >= 0 && g0 + 2 < HH) ? 1.0f : 0.0f);
        }
    }

    ull d0A = 0, d0B = 0, d1A = 0, d1B = 0;   // conv2 accumulators (2 rows x 2 pairs)

    #pragma unroll 1
    for (int f = 0; f < 12; f++) {
        float* bw = (f & 1) ? buf1 : buf0;

        // -------- stage A: conv1 + LUT + scale --------
        if (tid < 108) {
            const float2* cf = &sfa[f * 30];
            ull A0 = 0, B0 = 0, A1 = 0, B1 = 0, A2 = 0, B2 = 0;
            ull cc[5], cp[5], cq[5];
            #pragma unroll
            for (int k = 0; k < 7; k++) {
                LOADROW(su + (p0 + k) * 40 + q0);
                if (k <= 4) {
                    LOADCOEF(cf, k, cc);
                    CONV5(A0, B0, cc, E0, O0, E1, O1, E2, O2, E3);
                }
                if (k >= 1 && k <= 5) CONV5(A1, B1, cp, E0, O0, E1, O1, E2, O2, E3);
                if (k >= 2)           CONV5(A2, B2, cq, E0, O0, E1, O1, E2, O2, E3);
                #pragma unroll
                for (int t = 0; t < 5; t++) { cq[t] = cp[t]; cp[t] = cc[t]; }
            }
            float c0, c1, c2, c3;
            float4 res;
            unpack2(A0, c0, c1); unpack2(B0, c2, c3);
            res.x = lutphi(c0) * us0[0]; res.y = lutphi(c1) * us0[1];
            res.z = lutphi(c2) * us0[2]; res.w = lutphi(c3) * us0[3];
            *(float4*)(bw + p0 * 40 + q0) = res;
            unpack2(A1, c0, c1); unpack2(B1, c2, c3);
            res.x = lutphi(c0) * us1[0]; res.y = lutphi(c1) * us1[1];
            res.z = lutphi(c2) * us1[2]; res.w = lutphi(c3) * us1[3];
            *(float4*)(bw + (p0 + 1) * 40 + q0) = res;
            unpack2(A2, c0, c1); unpack2(B2, c2, c3);
            res.x = lutphi(c0) * us2[0]; res.y = lutphi(c1) * us2[1];
            res.z = lutphi(c2) * us2[2]; res.w = lutphi(c3) * us2[3];
            *(float4*)(bw + (p0 + 2) * 40 + q0) = res;
        }
        __syncthreads();

        // -------- stage B: conv2 accumulate --------
        if (tid < 120) {
            const float2* cf = &sfb[f * 30];
            ull cc[5], cp[5];
            #pragma unroll
            for (int k = 0; k < 6; k++) {
                LOADROW(bw + (oy0 + k) * 40 + ox0);
                if (k <= 4) {
                    LOADCOEF(cf, k, cc);
                    CONV5(d0A, d0B, cc, E0, O0, E1, O1, E2, O2, E3);
                }
                if (k >= 1) CONV5(d1A, d1B, cp, E0, O0, E1, O1, E2, O2, E3);
                #pragma unroll
                for (int t = 0; t < 5; t++) cp[t] = cc[t];
            }
        }
    }

    // -------- epilogue: write partial diffusion --------
    if (tid < 120) {
        float a0, a1, b0, b1;
        float* pp = &d_part[half][(b * HH + gy0 + oy0) * PW + gx0 + ox0];
        unpack2(d0A, a0, a1); unpack2(d0B, b0, b1);
        *(float2*)pp = make_float2(a0, a1);
        if (ox0 < 28) *(float2*)(pp + 2) = make_float2(b0, b1);
        pp += PW;
        unpack2(d1A, a0, a1); unpack2(d1B, b0, b1);
        *(float2*)pp = make_float2(a0, a1);
        if (ox0 < 28) *(float2*)(pp + 2) = make_float2(b0, b1);
    }
}

// ---------------- combine: sum halves + reaction + clip ----------------
__global__ void k_combine(const float* __restrict__ u,
                          const float* __restrict__ fin,
                          const float* __restrict__ lam,
                          float* __restrict__ out) {
    __shared__ float sv[2];
    if (threadIdx.x == 0) {
        float s = 0.0f;
        #pragma unroll 1
        for (int i = 0; i < 96; i++) s += d_bsums[i];
        float M = s * (1.0f / (9.0f * (float)NPIX)) + 0.001f;
        sv[0] = 1.0f / (9.0f * M);
        sv[1] = __ldg(lam);
    }
    __syncthreads();
    const float sc = sv[0], lamv = sv[1];
    const int NG = BB * HH * 45;
    for (int g = blockIdx.x * blockDim.x + threadIdx.x; g < NG;
         g += gridDim.x * blockDim.x) {
        int b = g / (HH * 45);
        int r = g - b * (HH * 45);
        int gy = r / 45;
        int gx = (r - gy * 45) * 4;
        int idx = b * PIX + gy * WW + gx;
        int pidx = (b * HH + gy) * PW + gx;
        float4 uu = *(const float4*)(u + idx);
        float4 ff = *(const float4*)(fin + idx);
        float4 p0 = *(const float4*)(&d_part[0][pidx]);
        float4 p1 = *(const float4*)(&d_part[1][pidx]);
        float4 o;
        {
            float re = lamv * (uu.x - ff.x) / (uu.x * uu.x + 1e-3f);
            o.x = fminf(fmaxf(uu.x - (p0.x + p1.x) * sc - re, 0.0f), 1.0f);
        }
        {
            float re = lamv * (uu.y - ff.y) / (uu.y * uu.y + 1e-3f);
            o.y = fminf(fmaxf(uu.y - (p0.y + p1.y) * sc - re, 0.0f), 1.0f);
        }
        {
            float re = lamv * (uu.z - ff.z) / (uu.z * uu.z + 1e-3f);
            o.z = fminf(fmaxf(uu.z - (p0.z + p1.z) * sc - re, 0.0f), 1.0f);
        }
        {
            float re = lamv * (uu.w - ff.w) / (uu.w * uu.w + 1e-3f);
            o.w = fminf(fmaxf(uu.w - (p0.w + p1.w) * sc - re, 0.0f), 1.0f);
        }
        *(float4*)(out + idx) = o;
    }
}

// ---------------- launch ----------------
extern "C" void kernel_launch(void* const* d_in, const int* in_sizes, int n_in,
                              void* d_out, int out_size) {
    const float* u       = (const float*)d_in[0];
    const float* f       = (const float*)d_in[1];
    const float* filters = (const float*)d_in[2];
    const float* lam     = (const float*)d_in[3];
    const float* mu      = (const float*)d_in[4];
    const float* weights = (const float*)d_in[5];
    float* out = (float*)d_out;

    k_pre<<<160, 256>>>(filters, mu, weights, u);

    dim3 grid(WW / 30, HH / 30, BB * 2);   // 6 x 6 x 16 = 576 blocks
    k_fused<<<grid, 128>>>(u);

    k_combine<<<128, 256>>>(u, f, lam, out);
}

// round 5
// speedup vs baseline: 1.2316x; 1.0498x over previous
#include <cuda_runtime.h>
#include <cstdint>

#define BB 8
#define HH 180
#define WW 180
#define NF 24
#define NB 31
#define NLUT 16384
#define PIX (HH*WW)
#define NPIX (BB*PIX)
#define PW 184

typedef unsigned long long ull;

// ---------------- device globals ----------------
__device__ float2 d_lut[NLUT];
__device__ float2 d_fA[NF*30];
__device__ float2 d_fB[NF*30];
__device__ float  d_bsums[96];
__device__ float  d_part[2][BB*HH*PW];

// ---------------- f32x2 helpers ----------------
__device__ __forceinline__ ull fma2(ull a, ull b, ull c) {
    ull d;
    asm("fma.rn.f32x2 %0, %1, %2, %3;" : "=l"(d) : "l"(a), "l"(b), "l"(c));
    return d;
}
__device__ __forceinline__ ull pack2(float lo, float hi) {
    ull r;
    asm("mov.b64 %0, {%1, %2};" : "=l"(r) : "f"(lo), "f"(hi));
    return r;
}
__device__ __forceinline__ void unpack2(ull v, float& lo, float& hi) {
    asm("mov.b64 {%0, %1}, %2;" : "=f"(lo), "=f"(hi) : "l"(v));
}

__device__ __forceinline__ float lutphi(float x) {
    float t = fmaf(x, 4096.0f, 8192.0f);
    t = fminf(fmaxf(t, 0.0f), 16383.5f);
    int ii = (int)t;
    float fr = t - (float)ii;
    float2 L = __ldg(&d_lut[ii]);
    return fmaf(fr, L.y, L.x);
}

__device__ __forceinline__ float rbf_eval(float x, const float* mu, const float* w) {
    float y = 0.0f;
    #pragma unroll
    for (int j = 0; j < NB; j++) {
        float t = x - __ldg(&mu[j]);
        y += __ldg(&w[j]) * __expf(-50.0f * t * t);
    }
    return y;
}

// ---------------- K0: prep (LUT via shared endpoints) + M reduction ----------------
__global__ void k_pre(const float* __restrict__ filters,
                      const float* __restrict__ mu,
                      const float* __restrict__ weights,
                      const float* __restrict__ u) {
    const int blk = blockIdx.x, tid = threadIdx.x;
    if (blk < 64) {
        __shared__ float sy[257];
        const int i = blk * 256 + tid;
        const float h = 4.0f / (float)NLUT;
        sy[tid] = rbf_eval(fmaf((float)i, h, -2.0f), mu, weights);
        if (tid == 0)
            sy[256] = rbf_eval(fmaf((float)(blk * 256 + 256), h, -2.0f), mu, weights);
        __syncthreads();
        d_lut[i] = make_float2(sy[tid], sy[tid + 1] - sy[tid]);

        if (blk < 3) {
            int t = blk * 256 + tid;
            if (t < NF * 30) {
                int f = t / 30, e = t % 30;
                int r = e / 6, c = e % 6;
                float wA = 0.0f, wB = 0.0f;
                if (c < 5) {
                    wA = __ldg(&filters[f * 25 + r * 5 + c]);
                    wB = __ldg(&filters[f * 25 + (4 - r) * 5 + (4 - c)]);
                }
                d_fA[t] = make_float2(wA, wA);
                d_fB[t] = make_float2(wB, wB);
            }
        }
    } else {
        const int NG = BB * HH * 45;
        float s = 0.0f;
        for (int g = (blk - 64) * 256 + tid; g < NG; g += 96 * 256) {
            int b = g / (HH * 45);
            int r = g - b * (HH * 45);
            int gy = r / 45;
            int gx = (r - gy * 45) * 4;
            const float4 uu = *(const float4*)(u + b * PIX + gy * WW + gx);
            float wy = (gy == 0 || gy == HH - 1) ? 2.0f : 3.0f;
            float w0 = (gx == 0) ? 2.0f : 3.0f;
            float w3 = (gx + 3 == WW - 1) ? 2.0f : 3.0f;
            s += wy * (w0 * uu.x + 3.0f * uu.y + 3.0f * uu.z + w3 * uu.w);
        }
        #pragma unroll
        for (int o = 16; o > 0; o >>= 1) s += __shfl_xor_sync(0xFFFFFFFFu, s, o);
        __shared__ float ws[8];
        int wid = tid >> 5, lane = tid & 31;
        if (lane == 0) ws[wid] = s;
        __syncthreads();
        if (tid == 0) {
            float bs = 0.0f;
            #pragma unroll
            for (int w = 0; w < 8; w++) bs += ws[w];
            d_bsums[blk - 64] = bs;
        }
    }
}

// ---------------- conv building blocks ----------------
#define CONV5(a0, a1, C, E0, O0, E1, O1, E2, O2, E3)                         \
    do {                                                                     \
        a0 = fma2((C)[0], E0, a0); a0 = fma2((C)[1], O0, a0);                \
        a0 = fma2((C)[2], E1, a0); a0 = fma2((C)[3], O1, a0);                \
        a0 = fma2((C)[4], E2, a0);                                           \
        a1 = fma2((C)[0], E1, a1); a1 = fma2((C)[1], O1, a1);                \
        a1 = fma2((C)[2], E2, a1); a1 = fma2((C)[3], O2, a1);                \
        a1 = fma2((C)[4], E3, a1);                                           \
    } while (0)

#define LOADROW(base)                                                        \
    const ulonglong2* rp_ = (const ulonglong2*)(base);                       \
    ulonglong2 ra_ = rp_[0], rb_ = rp_[1];                                   \
    ull E0 = ra_.x, E1 = ra_.y, E2 = rb_.x, E3 = rb_.y;                      \
    float v0, v1, v2, v3, v4, v5, v6, v7;                                    \
    unpack2(E0, v0, v1); unpack2(E1, v2, v3);                                \
    unpack2(E2, v4, v5); unpack2(E3, v6, v7);                                \
    ull O0 = pack2(v1, v2), O1 = pack2(v3, v4), O2 = pack2(v5, v6);          \
    (void)v0; (void)v7;

#define LOADCOEF(cf, k, cc)                                                  \
    do {                                                                     \
        const ulonglong2* cv_ = (const ulonglong2*)((cf) + (k) * 6);         \
        ulonglong2 x0_ = cv_[0], x1_ = cv_[1];                               \
        cc[0] = x0_.x; cc[1] = x0_.y; cc[2] = x1_.x; cc[3] = x1_.y;          \
        cc[4] = *(const ull*)((cf) + (k) * 6 + 4);                           \
    } while (0)

__device__ __forceinline__ void stageA(const float* __restrict__ su,
                                       const float2* __restrict__ cf,
                                       float* __restrict__ bw,
                                       int p0, int q0,
                                       const float us0[4], const float us1[4],
                                       const float us2[4]) {
    ull A0 = 0, B0 = 0, A1 = 0, B1 = 0, A2 = 0, B2 = 0;
    ull cc[5], cp[5], cq[5];
    #pragma unroll
    for (int k = 0; k < 7; k++) {
        LOADROW(su + (p0 + k) * 40 + q0);
        if (k <= 4) {
            LOADCOEF(cf, k, cc);
            CONV5(A0, B0, cc, E0, O0, E1, O1, E2, O2, E3);
        }
        if (k >= 1 && k <= 5) CONV5(A1, B1, cp, E0, O0, E1, O1, E2, O2, E3);
        if (k >= 2)           CONV5(A2, B2, cq, E0, O0, E1, O1, E2, O2, E3);
        #pragma unroll
        for (int t = 0; t < 5; t++) { cq[t] = cp[t]; cp[t] = cc[t]; }
    }
    float c0, c1, c2, c3;
    float4 res;
    unpack2(A0, c0, c1); unpack2(B0, c2, c3);
    res.x = lutphi(c0) * us0[0]; res.y = lutphi(c1) * us0[1];
    res.z = lutphi(c2) * us0[2]; res.w = lutphi(c3) * us0[3];
    *(float4*)(bw + p0 * 40 + q0) = res;
    unpack2(A1, c0, c1); unpack2(B1, c2, c3);
    res.x = lutphi(c0) * us1[0]; res.y = lutphi(c1) * us1[1];
    res.z = lutphi(c2) * us1[2]; res.w = lutphi(c3) * us1[3];
    *(float4*)(bw + (p0 + 1) * 40 + q0) = res;
    unpack2(A2, c0, c1); unpack2(B2, c2, c3);
    res.x = lutphi(c0) * us2[0]; res.y = lutphi(c1) * us2[1];
    res.z = lutphi(c2) * us2[2]; res.w = lutphi(c3) * us2[3];
    *(float4*)(bw + (p0 + 2) * 40 + q0) = res;
}

__device__ __forceinline__ void stageB(const float* __restrict__ bw,
                                       const float2* __restrict__ cf,
                                       int oy0, int ox0,
                                       ull& d0A, ull& d0B, ull& d1A, ull& d1B) {
    ull cc[5], cp[5];
    #pragma unroll
    for (int k = 0; k < 6; k++) {
        LOADROW(bw + (oy0 + k) * 40 + ox0);
        if (k <= 4) {
            LOADCOEF(cf, k, cc);
            CONV5(d0A, d0B, cc, E0, O0, E1, O1, E2, O2, E3);
        }
        if (k >= 1) CONV5(d1A, d1B, cp, E0, O0, E1, O1, E2, O2, E3);
        #pragma unroll
        for (int t = 0; t < 5; t++) cp[t] = cc[t];
    }
}

// ---------------- fused kernel: 12 filters per block, 2 per phase ----------------
__global__ __launch_bounds__(128, 4) void k_fused(const float* __restrict__ u) {
    __shared__ __align__(16) float su[40 * 40];
    __shared__ __align__(16) float bufs[4][36 * 40];
    __shared__ __align__(16) float2 sfa[12 * 30];
    __shared__ __align__(16) float2 sfb[12 * 30];

    const int tid = threadIdx.x;
    const int half = blockIdx.z & 1;
    const int b = blockIdx.z >> 1;
    const int f0 = half * 12;
    const int gx0 = blockIdx.x * 30;
    const int gy0 = blockIdx.y * 30;

    for (int i = tid; i < 360; i += 128) {
        sfa[i] = d_fA[f0 * 30 + i];
        sfb[i] = d_fB[f0 * 30 + i];
    }

    const float* ub = u + b * PIX;
    for (int i = tid; i < 1600; i += 128) {
        int r = i / 40, c = i % 40;
        int gy = gy0 - 4 + r, gx = gx0 - 4 + c;
        float v = 0.0f;
        if (gy >= 0 && gy < HH && gx >= 0 && gx < WW) v = __ldg(&ub[gy * WW + gx]);
        su[i] = v;
    }
    __syncthreads();

    const int p0 = (tid / 9) * 3;
    const int q0 = (tid % 9) * 4;
    const int oy0 = (tid >> 3) * 2;
    const int ox0 = (tid & 7) * 4;

    // hoisted boxsum with masks folded in
    float us0[4] = {0, 0, 0, 0}, us1[4] = {0, 0, 0, 0}, us2[4] = {0, 0, 0, 0};
    if (tid < 108) {
        #pragma unroll
        for (int k = 1; k <= 5; k++) {
            const float4* rp = (const float4*)(su + (p0 + k) * 40 + q0);
            float4 a = rp[0], bq = rp[1];
            float a_ = a.z + a.w, b_ = bq.x + bq.y;
            float hs0 = a.y + a_, hs1 = a_ + bq.x, hs2 = a.w + b_, hs3 = b_ + bq.z;
            if (k <= 3)           { us0[0] += hs0; us0[1] += hs1; us0[2] += hs2; us0[3] += hs3; }
            if (k >= 2 && k <= 4) { us1[0] += hs0; us1[1] += hs1; us1[2] += hs2; us1[3] += hs3; }
            if (k >= 3)           { us2[0] += hs0; us2[1] += hs1; us2[2] += hs2; us2[3] += hs3; }
        }
        #pragma unroll
        for (int j = 0; j < 4; j++) {
            int gx = gx0 - 2 + q0 + j;
            float cm = (gx >= 0 && gx < WW) ? 1.0f : 0.0f;
            int g0 = gy0 - 2 + p0;
            us0[j] *= cm * ((g0 >= 0 && g0 < HH) ? 1.0f : 0.0f);
            us1[j] *= cm * ((g0 + 1 >= 0 && g0 + 1 < HH) ? 1.0f : 0.0f);
            us2[j] *= cm * ((g0 + 2 >= 0 && g0 + 2 < HH) ? 1.0f : 0.0f);
        }
    }

    ull d0A = 0, d0B = 0, d1A = 0, d1B = 0;

    #pragma unroll 1
    for (int g = 0; g < 6; g++) {
        const int fa = 2 * g, fb = 2 * g + 1;
        float* bwA = bufs[fa & 3];
        float* bwB = bufs[fb & 3];

        if (tid < 108) {
            stageA(su, &sfa[fa * 30], bwA, p0, q0, us0, us1, us2);
            stageA(su, &sfa[fb * 30], bwB, p0, q0, us0, us1, us2);
        }
        __syncthreads();
        if (tid < 120) {
            stageB(bwA, &sfb[fa * 30], oy0, ox0, d0A, d0B, d1A, d1B);
            stageB(bwB, &sfb[fb * 30], oy0, ox0, d0A, d0B, d1A, d1B);
        }
    }

    if (tid < 120) {
        float a0, a1, b0, b1;
        float* pp = &d_part[half][(b * HH + gy0 + oy0) * PW + gx0 + ox0];
        unpack2(d0A, a0, a1); unpack2(d0B, b0, b1);
        *(float2*)pp = make_float2(a0, a1);
        if (ox0 < 28) *(float2*)(pp + 2) = make_float2(b0, b1);
        pp += PW;
        unpack2(d1A, a0, a1); unpack2(d1B, b0, b1);
        *(float2*)pp = make_float2(a0, a1);
        if (ox0 < 28) *(float2*)(pp + 2) = make_float2(b0, b1);
    }
}

// ---------------- combine ----------------
__global__ void k_combine(const float* __restrict__ u,
                          const float* __restrict__ fin,
                          const float* __restrict__ lam,
                          float* __restrict__ out) {
    __shared__ float sv[2];
    __shared__ float wsum[3];
    {
        const int tid = threadIdx.x;
        float s = (tid < 96) ? d_bsums[tid] : 0.0f;
        #pragma unroll
        for (int o = 16; o > 0; o >>= 1) s += __shfl_xor_sync(0xFFFFFFFFu, s, o);
        if ((tid & 31) == 0 && tid < 96) wsum[tid >> 5] = s;
        __syncthreads();
        if (tid == 0) {
            float t = wsum[0] + wsum[1] + wsum[2];
            float M = t * (1.0f / (9.0f * (float)NPIX)) + 0.001f;
            sv[0] = 1.0f / (9.0f * M);
            sv[1] = __ldg(lam);
        }
        __syncthreads();
    }
    const float sc = sv[0], lamv = sv[1];
    const int NG = BB * HH * 45;
    for (int g = blockIdx.x * blockDim.x + threadIdx.x; g < NG;
         g += gridDim.x * blockDim.x) {
        int b = g / (HH * 45);
        int r = g - b * (HH * 45);
        int gy = r / 45;
        int gx = (r - gy * 45) * 4;
        int idx = b * PIX + gy * WW + gx;
        int pidx = (b * HH + gy) * PW + gx;
        float4 uu = *(const float4*)(u + idx);
        float4 ff = *(const float4*)(fin + idx);
        float4 p0 = *(const float4*)(&d_part[0][pidx]);
        float4 p1 = *(const float4*)(&d_part[1][pidx]);
        float4 o;
        o.x = fminf(fmaxf(uu.x - (p0.x + p1.x) * sc - lamv * (uu.x - ff.x) / (uu.x * uu.x + 1e-3f), 0.0f), 1.0f);
        o.y = fminf(fmaxf(uu.y - (p0.y + p1.y) * sc - lamv * (uu.y - ff.y) / (uu.y * uu.y + 1e-3f), 0.0f), 1.0f);
        o.z = fminf(fmaxf(uu.z - (p0.z + p1.z) * sc - lamv * (uu.z - ff.z) / (uu.z * uu.z + 1e-3f), 0.0f), 1.0f);
        o.w = fminf(fmaxf(uu.w - (p0.w + p1.w) * sc - lamv * (uu.w - ff.w) / (uu.w * uu.w + 1e-3f), 0.0f), 1.0f);
        *(float4*)(out + idx) = o;
    }
}

// ---------------- launch ----------------
extern "C" void kernel_launch(void* const* d_in, const int* in_sizes, int n_in,
                              void* d_out, int out_size) {
    const float* u       = (const float*)d_in[0];
    const float* f       = (const float*)d_in[1];
    const float* filters = (const float*)d_in[2];
    const float* lam     = (const float*)d_in[3];
    const float* mu      = (const float*)d_in[4];
    const float* weights = (const float*)d_in[5];
    float* out = (float*)d_out;

    k_pre<<<160, 256>>>(filters, mu, weights, u);

    dim3 grid(WW / 30, HH / 30, BB * 2);   // 576 blocks
    k_fused<<<grid, 128>>>(u);

    k_combine<<<128, 256>>>(u, f, lam, out);
}